// round 2
// baseline (speedup 1.0000x reference)
#include <cuda_runtime.h>
#include <math.h>

// ---------------- problem constants (fixed by dataset shapes) ----------------
#define T_TOK 64
#define S_SP  729
#define H_DIM 1152
#define E_DIM 512
#define NE    9
#define NL    4
#define B_IMG 8
#define P_PAT 8

#define OUT_MAJOR 0
#define OUT_FINAL (T_TOK * 4 * H_DIM)                 // 294912
#define OUT_PREDS (OUT_FINAL + B_IMG * H_DIM)         // 304128

// ---------------- device scratch (static: no allocation allowed) -------------
__device__ float g_pooled [B_IMG * H_DIM];
__device__ float g_hidden [B_IMG * E_DIM];
__device__ float g_cls    [B_IMG * E_DIM];
__device__ float g_prompts[NL * B_IMG * NE * E_DIM];
__device__ float g_scores [(size_t)NL * T_TOK * NE * S_SP];   // 6.7 MB
__device__ float g_meanatt[T_TOK * NE * S_SP];
__device__ float g_pes    [T_TOK * NE];
__device__ float g_gsig   [T_TOK * 4];
__device__ float g_tokens [T_TOK * 4 * H_DIM];
__device__ float g_K      [(size_t)T_TOK * S_SP * E_DIM];     // 95.5 MB
__device__ float g_Q      [T_TOK * 4 * E_DIM];
__device__ float g_final  [B_IMG * H_DIM];

// ---------------- block reduction helpers (blockDim == 256) ------------------
__device__ __forceinline__ float blockSum256(float v) {
    __shared__ float red[8];
    int lane = threadIdx.x & 31, wid = threadIdx.x >> 5;
    #pragma unroll
    for (int o = 16; o; o >>= 1) v += __shfl_xor_sync(0xffffffffu, v, o);
    if (lane == 0) red[wid] = v;
    __syncthreads();
    if (wid == 0) {
        float r = (lane < 8) ? red[lane] : 0.f;
        #pragma unroll
        for (int o = 4; o; o >>= 1) r += __shfl_xor_sync(0xffffffffu, r, o);
        if (lane == 0) red[0] = r;
    }
    __syncthreads();
    float r = red[0];
    __syncthreads();
    return r;
}

__device__ __forceinline__ float blockMax256(float v) {
    __shared__ float red[8];
    int lane = threadIdx.x & 31, wid = threadIdx.x >> 5;
    #pragma unroll
    for (int o = 16; o; o >>= 1) v = fmaxf(v, __shfl_xor_sync(0xffffffffu, v, o));
    if (lane == 0) red[wid] = v;
    __syncthreads();
    if (wid == 0) {
        float r = (lane < 8) ? red[lane] : -INFINITY;
        #pragma unroll
        for (int o = 4; o; o >>= 1) r = fmaxf(r, __shfl_xor_sync(0xffffffffu, r, o));
        if (lane == 0) red[0] = r;
    }
    __syncthreads();
    float r = red[0];
    __syncthreads();
    return r;
}

__device__ __forceinline__ float gelu_exact(float x) {
    return 0.5f * x * (1.0f + erff(x * 0.7071067811865475f));
}

// ---------------- P0: pooled[b,h] = sum_s pool_w[s] * ov[b*8, s, h] + pool_b --
__global__ void k_pool(const float* __restrict__ ov, const float* __restrict__ pw,
                       const float* __restrict__ pb) {
    int b = blockIdx.x, tid = threadIdx.x;
    int nh = (tid < 128) ? 5 : 4;   // 1152 = 4*256 + 128
    float acc[5] = {0, 0, 0, 0, 0};
    const float* base = ov + (size_t)(b * P_PAT) * S_SP * H_DIM + tid;
    for (int s = 0; s < S_SP; s++) {
        float w = pw[s];
        const float* p = base + (size_t)s * H_DIM;
        #pragma unroll
        for (int j = 0; j < 5; j++)
            if (j < nh) acc[j] += w * p[j * 256];
    }
    float bias = pb[0];
    for (int j = 0; j < nh; j++)
        g_pooled[b * H_DIM + tid + j * 256] = acc[j] + bias;
}

// ---------------- P1a: hidden = gelu(pooled @ cls_w1^T + b1) ------------------
__global__ void k_cls1(const float* __restrict__ w1, const float* __restrict__ b1) {
    int b = blockIdx.x, tid = threadIdx.x;
    __shared__ float pr[H_DIM];
    for (int i = tid; i < H_DIM; i += 256) pr[i] = g_pooled[b * H_DIM + i];
    __syncthreads();
    int wid = tid >> 5, lane = tid & 31;
    for (int o = wid; o < E_DIM; o += 8) {
        float acc = 0.f;
        const float* wr = w1 + (size_t)o * H_DIM;
        for (int k = lane; k < H_DIM; k += 32) acc += wr[k] * pr[k];
        #pragma unroll
        for (int off = 16; off; off >>= 1) acc += __shfl_xor_sync(0xffffffffu, acc, off);
        if (lane == 0) g_hidden[b * E_DIM + o] = gelu_exact(acc + b1[o]);
    }
}

// ---------------- P1b: cls = hidden @ cls_w2^T + b2 ---------------------------
__global__ void k_cls2(const float* __restrict__ w2, const float* __restrict__ b2) {
    int b = blockIdx.x, tid = threadIdx.x;
    __shared__ float hr[E_DIM];
    for (int i = tid; i < E_DIM; i += 256) hr[i] = g_hidden[b * E_DIM + i];
    __syncthreads();
    int wid = tid >> 5, lane = tid & 31;
    for (int o = wid; o < E_DIM; o += 8) {
        float acc = 0.f;
        const float* wr = w2 + (size_t)o * E_DIM;
        for (int k = lane; k < E_DIM; k += 32) acc += wr[k] * hr[k];
        #pragma unroll
        for (int off = 16; off; off >>= 1) acc += __shfl_xor_sync(0xffffffffu, acc, off);
        if (lane == 0) g_cls[b * E_DIM + o] = acc + b2[o];
    }
}

// ---------------- P2: prompts[i,b,n,:] = l2norm(pw[i] @ cat(emo[n],cls[b]) + pb[i])
__global__ void k_prompts(const float* __restrict__ emo, const float* __restrict__ pw,
                          const float* __restrict__ pb) {
    int n = blockIdx.x, b = blockIdx.y, i = blockIdx.z;
    int tid = threadIdx.x;
    __shared__ float cat[1024];
    __shared__ float raw[E_DIM];
    for (int idx = tid; idx < 1024; idx += 256)
        cat[idx] = (idx < 512) ? emo[n * 512 + idx] : g_cls[b * 512 + (idx - 512)];
    __syncthreads();
    int wid = tid >> 5, lane = tid & 31;
    for (int o = wid; o < E_DIM; o += 8) {
        float acc = 0.f;
        const float* wr = pw + ((size_t)i * E_DIM + o) * 1024;
        for (int c = lane; c < 1024; c += 32) acc += wr[c] * cat[c];
        #pragma unroll
        for (int off = 16; off; off >>= 1) acc += __shfl_xor_sync(0xffffffffu, acc, off);
        if (lane == 0) raw[o] = acc + pb[i * E_DIM + o];
    }
    __syncthreads();
    float v = raw[tid] * raw[tid] + raw[tid + 256] * raw[tid + 256];
    float nrm = blockSum256(v);
    float inv = rsqrtf(nrm);
    size_t base = ((size_t)(i * B_IMG + b) * NE + n) * E_DIM;
    g_prompts[base + tid] = raw[tid] * inv;
    g_prompts[base + tid + 256] = raw[tid + 256] * inv;
}

// ---------------- A: big GEMM + norm + prompt-dot epilogue -> scores ----------
// grid (23, 64, 4), block 256.  tile: M=32 (spatial rows), N=512, K-step 16.
__global__ void k_sig_scores(const float* __restrict__ sig, const float* __restrict__ sw,
                             const float* __restrict__ sb) {
    extern __shared__ float sm[];
    float* As  = sm;            // [16][32]
    float* Ws  = sm + 512;      // [16][512]
    float* ysh = sm;            // [32][512] (reuse after mainloop)
    float* Psm = sm + 16384;    // [9][512]

    int tid = threadIdx.x;
    int s0 = blockIdx.x * 32;
    int t  = blockIdx.y;
    int i  = blockIdx.z;
    int b  = t >> 3;

    // prompts for this (i,b) into smem
    {
        size_t pbase = ((size_t)(i * B_IMG + b) * NE) * E_DIM;
        for (int idx = tid; idx < NE * E_DIM; idx += 256) Psm[idx] = g_prompts[pbase + idx];
    }

    int tr = tid >> 6;          // 0..3 -> rows tr*8..tr*8+7
    int tc = tid & 63;          // 0..63 -> cols tc*8..tc*8+7
    float acc[8][8];
    #pragma unroll
    for (int a = 0; a < 8; a++)
        #pragma unroll
        for (int c = 0; c < 8; c++) acc[a][c] = 0.f;

    const float* Abase = sig + ((size_t)(i * T_TOK + t) * S_SP) * H_DIM;
    const float* Wbase = sw + (size_t)i * E_DIM * H_DIM;

    for (int kt = 0; kt < H_DIM / 16; kt++) {
        // load A tile [16k][32r]
        {
            int idx = tid * 2;
            int r = idx >> 4, kk = idx & 15;
            int s = s0 + r;
            float2 v = make_float2(0.f, 0.f);
            if (s < S_SP)
                v = *reinterpret_cast<const float2*>(Abase + (size_t)s * H_DIM + kt * 16 + kk);
            As[kk * 32 + r] = v.x;
            As[(kk + 1) * 32 + r] = v.y;
        }
        // load W tile [16k][512o]
        #pragma unroll
        for (int j = 0; j < 16; j++) {
            int lin = tid + j * 256;
            int o = lin >> 3, kk = (lin & 7) << 1;
            float2 v = *reinterpret_cast<const float2*>(Wbase + (size_t)o * H_DIM + kt * 16 + kk);
            Ws[kk * 512 + o] = v.x;
            Ws[(kk + 1) * 512 + o] = v.y;
        }
        __syncthreads();
        #pragma unroll
        for (int k = 0; k < 16; k++) {
            const float4* a4 = reinterpret_cast<const float4*>(&As[k * 32 + tr * 8]);
            float4 av0 = a4[0], av1 = a4[1];
            const float4* w4 = reinterpret_cast<const float4*>(&Ws[k * 512 + tc * 8]);
            float4 wv0 = w4[0], wv1 = w4[1];
            float a[8] = {av0.x, av0.y, av0.z, av0.w, av1.x, av1.y, av1.z, av1.w};
            float w[8] = {wv0.x, wv0.y, wv0.z, wv0.w, wv1.x, wv1.y, wv1.z, wv1.w};
            #pragma unroll
            for (int ii = 0; ii < 8; ii++)
                #pragma unroll
                for (int jj = 0; jj < 8; jj++) acc[ii][jj] += a[ii] * w[jj];
        }
        __syncthreads();
    }

    // bias + stage y tile to smem
    float bias[8];
    #pragma unroll
    for (int jj = 0; jj < 8; jj++) bias[jj] = sb[i * E_DIM + tc * 8 + jj];
    #pragma unroll
    for (int ii = 0; ii < 8; ii++) {
        float4 v0 = make_float4(acc[ii][0] + bias[0], acc[ii][1] + bias[1],
                                acc[ii][2] + bias[2], acc[ii][3] + bias[3]);
        float4 v1 = make_float4(acc[ii][4] + bias[4], acc[ii][5] + bias[5],
                                acc[ii][6] + bias[6], acc[ii][7] + bias[7]);
        float* dst = &ysh[(size_t)(tr * 8 + ii) * 512 + tc * 8];
        *reinterpret_cast<float4*>(dst) = v0;
        *reinterpret_cast<float4*>(dst + 4) = v1;
    }
    __syncthreads();

    // per-row: norm + 9 prompt dots -> scores
    int wid = tid >> 5, lane = tid & 31;
    for (int gseg = 0; gseg < 4; gseg++) {
        int r = gseg * 8 + wid;
        int s = s0 + r;
        if (s >= S_SP) continue;
        float nsq = 0.f;
        float d[NE];
        #pragma unroll
        for (int n = 0; n < NE; n++) d[n] = 0.f;
        #pragma unroll
        for (int m = 0; m < 16; m++) {
            int o = lane + m * 32;
            float y = ysh[(size_t)r * 512 + o];
            nsq += y * y;
            #pragma unroll
            for (int n = 0; n < NE; n++) d[n] += y * Psm[n * 512 + o];
        }
        #pragma unroll
        for (int off = 16; off; off >>= 1) {
            nsq += __shfl_xor_sync(0xffffffffu, nsq, off);
            #pragma unroll
            for (int n = 0; n < NE; n++) d[n] += __shfl_xor_sync(0xffffffffu, d[n], off);
        }
        if (lane == 0) {
            float inv = rsqrtf(nsq);
            size_t base = ((size_t)(i * T_TOK + t) * NE) * S_SP + s;
            #pragma unroll
            for (int n = 0; n < NE; n++) g_scores[base + (size_t)n * S_SP] = 100.f * d[n] * inv;
        }
    }
}

// ---------------- B: softmax over s per (i,t,n), mean over levels -------------
__global__ void k_softmax_mean() {
    int tn = blockIdx.x;          // t*9+n
    int t = tn / NE, n = tn % NE;
    int tid = threadIdx.x;
    float accm[3] = {0.f, 0.f, 0.f};
    for (int i = 0; i < NL; i++) {
        size_t base = ((size_t)(i * T_TOK + t) * NE + n) * S_SP;
        float x[3];
        float mx = -INFINITY;
        #pragma unroll
        for (int j = 0; j < 3; j++) {
            int s = tid + j * 256;
            x[j] = (s < S_SP) ? g_scores[base + s] : -INFINITY;
            mx = fmaxf(mx, x[j]);
        }
        mx = blockMax256(mx);
        float lsum = 0.f;
        float e[3];
        #pragma unroll
        for (int j = 0; j < 3; j++) {
            int s = tid + j * 256;
            e[j] = (s < S_SP) ? expf(x[j] - mx) : 0.f;
            lsum += e[j];
        }
        float tot = blockSum256(lsum);
        float inv = 0.25f / tot;
        #pragma unroll
        for (int j = 0; j < 3; j++) accm[j] += e[j] * inv;
    }
    float psum = 0.f;
    size_t obase = ((size_t)t * NE + n) * S_SP;
    #pragma unroll
    for (int j = 0; j < 3; j++) {
        int s = tid + j * 256;
        if (s < S_SP) {
            g_meanatt[obase + s] = accm[j];
            psum += accm[j];
        }
    }
    float tot = blockSum256(psum);
    if (tid == 0) g_pes[t * NE + n] = tot / (float)S_SP;
}

// ---------------- C: max over n, 2x2 pooling, tokens, global_sig --------------
__global__ void k_tokens(const float* __restrict__ ov) {
    int t = blockIdx.x, tid = threadIdx.x;
    __shared__ float matt[S_SP];
    __shared__ float sp[4];
    __shared__ float pmx;

    float bsum[4] = {0.f, 0.f, 0.f, 0.f};
    for (int s = tid; s < S_SP; s += 256) {
        float m = -INFINITY;
        #pragma unroll
        for (int n = 0; n < NE; n++)
            m = fmaxf(m, g_meanatt[((size_t)t * NE + n) * S_SP + s]);
        matt[s] = m;
        int r = s / 27, c = s - r * 27;
        bool r0 = r < 14, r1 = r >= 13, c0 = c < 14, c1 = c >= 13;
        if (r0 && c0) bsum[0] += m;
        if (r0 && c1) bsum[1] += m;
        if (r1 && c0) bsum[2] += m;
        if (r1 && c1) bsum[3] += m;
    }
    #pragma unroll
    for (int q = 0; q < 4; q++) {
        float tot = blockSum256(bsum[q]);
        if (tid == 0) sp[q] = tot / 196.f;
    }
    if (tid == 0) {
        float pm = -INFINITY;
        for (int n = 0; n < NE; n++) pm = fmaxf(pm, g_pes[t * NE + n]);
        pmx = pm;
    }
    __syncthreads();
    if (tid < 4) g_gsig[t * 4 + tid] = sp[tid] * pmx;

    // tokens
    int nh = (tid < 128) ? 5 : 4;
    float accT[5][4];
    #pragma unroll
    for (int j = 0; j < 5; j++)
        #pragma unroll
        for (int q = 0; q < 4; q++) accT[j][q] = 0.f;
    const float* obase = ov + ((size_t)t * S_SP) * H_DIM + tid;
    for (int s = 0; s < S_SP; s++) {
        float a = matt[s];
        int r = s / 27, c = s - r * 27;
        float w0 = (r < 14 && c < 14) ? a : 0.f;
        float w1 = (r < 14 && c >= 13) ? a : 0.f;
        float w2 = (r >= 13 && c < 14) ? a : 0.f;
        float w3 = (r >= 13 && c >= 13) ? a : 0.f;
        const float* p = obase + (size_t)s * H_DIM;
        #pragma unroll
        for (int j = 0; j < 5; j++) {
            if (j < nh) {
                float v = p[j * 256];
                accT[j][0] += v * w0;
                accT[j][1] += v * w1;
                accT[j][2] += v * w2;
                accT[j][3] += v * w3;
            }
        }
    }
    for (int j = 0; j < nh; j++) {
        int h = tid + j * 256;
        #pragma unroll
        for (int q = 0; q < 4; q++)
            g_tokens[((size_t)t * 4 + q) * H_DIM + h] =
                (accT[j][q] * (1.f / 196.f)) / (sp[q] + 1e-8f);
    }
}

// ---------------- D: K projection GEMM (same tiling as A) ---------------------
__global__ void k_kproj(const float* __restrict__ ov, const float* __restrict__ kw,
                        const float* __restrict__ kb) {
    extern __shared__ float sm[];
    float* As = sm;          // [16][32]
    float* Ws = sm + 512;    // [16][512]

    int tid = threadIdx.x;
    int s0 = blockIdx.x * 32;
    int t  = blockIdx.y;

    int tr = tid >> 6, tc = tid & 63;
    float acc[8][8];
    #pragma unroll
    for (int a = 0; a < 8; a++)
        #pragma unroll
        for (int c = 0; c < 8; c++) acc[a][c] = 0.f;

    const float* Abase = ov + ((size_t)t * S_SP) * H_DIM;

    for (int kt = 0; kt < H_DIM / 16; kt++) {
        {
            int idx = tid * 2;
            int r = idx >> 4, kk = idx & 15;
            int s = s0 + r;
            float2 v = make_float2(0.f, 0.f);
            if (s < S_SP)
                v = *reinterpret_cast<const float2*>(Abase + (size_t)s * H_DIM + kt * 16 + kk);
            As[kk * 32 + r] = v.x;
            As[(kk + 1) * 32 + r] = v.y;
        }
        #pragma unroll
        for (int j = 0; j < 16; j++) {
            int lin = tid + j * 256;
            int o = lin >> 3, kk = (lin & 7) << 1;
            float2 v = *reinterpret_cast<const float2*>(kw + (size_t)o * H_DIM + kt * 16 + kk);
            Ws[kk * 512 + o] = v.x;
            Ws[(kk + 1) * 512 + o] = v.y;
        }
        __syncthreads();
        #pragma unroll
        for (int k = 0; k < 16; k++) {
            const float4* a4 = reinterpret_cast<const float4*>(&As[k * 32 + tr * 8]);
            float4 av0 = a4[0], av1 = a4[1];
            const float4* w4 = reinterpret_cast<const float4*>(&Ws[k * 512 + tc * 8]);
            float4 wv0 = w4[0], wv1 = w4[1];
            float a[8] = {av0.x, av0.y, av0.z, av0.w, av1.x, av1.y, av1.z, av1.w};
            float w[8] = {wv0.x, wv0.y, wv0.z, wv0.w, wv1.x, wv1.y, wv1.z, wv1.w};
            #pragma unroll
            for (int ii = 0; ii < 8; ii++)
                #pragma unroll
                for (int jj = 0; jj < 8; jj++) acc[ii][jj] += a[ii] * w[jj];
        }
        __syncthreads();
    }

    float bias[8];
    #pragma unroll
    for (int jj = 0; jj < 8; jj++) bias[jj] = kb[tc * 8 + jj];
    #pragma unroll
    for (int ii = 0; ii < 8; ii++) {
        int s = s0 + tr * 8 + ii;
        if (s >= S_SP) continue;
        float* dst = &g_K[((size_t)t * S_SP + s) * E_DIM + tc * 8];
        float4 v0 = make_float4(acc[ii][0] + bias[0], acc[ii][1] + bias[1],
                                acc[ii][2] + bias[2], acc[ii][3] + bias[3]);
        float4 v1 = make_float4(acc[ii][4] + bias[4], acc[ii][5] + bias[5],
                                acc[ii][6] + bias[6], acc[ii][7] + bias[7]);
        *reinterpret_cast<float4*>(dst) = v0;
        *reinterpret_cast<float4*>(dst + 4) = v1;
    }
}

// ---------------- E: Q = tokens @ q_w^T + q_b ---------------------------------
__global__ void k_qproj(const float* __restrict__ qw, const float* __restrict__ qb) {
    int t = blockIdx.x, tid = threadIdx.x;
    __shared__ float toks[4 * H_DIM];
    for (int idx = tid; idx < 4 * H_DIM; idx += 256) toks[idx] = g_tokens[(size_t)t * 4 * H_DIM + idx];
    __syncthreads();
    int wid = tid >> 5, lane = tid & 31;
    for (int o = wid; o < E_DIM; o += 8) {
        float acc[4] = {0.f, 0.f, 0.f, 0.f};
        const float* wr = qw + (size_t)o * H_DIM;
        for (int k = lane; k < H_DIM; k += 32) {
            float w = wr[k];
            #pragma unroll
            for (int q = 0; q < 4; q++) acc[q] += w * toks[q * H_DIM + k];
        }
        #pragma unroll
        for (int off = 16; off; off >>= 1)
            #pragma unroll
            for (int q = 0; q < 4; q++) acc[q] += __shfl_xor_sync(0xffffffffu, acc[q], off);
        if (lane == 0) {
            float bv = qb[o];
            #pragma unroll
            for (int q = 0; q < 4; q++) g_Q[((size_t)t * 4 + q) * E_DIM + o] = acc[q] + bv;
        }
    }
}

// ---------------- F: q-former attention + major -------------------------------
__global__ void k_attn_major(const float* __restrict__ ov, float* __restrict__ out) {
    int t = blockIdx.x, tid = threadIdx.x;
    __shared__ float Qs[4 * E_DIM];
    __shared__ float law[4 * S_SP];
    for (int idx = tid; idx < 4 * E_DIM; idx += 256) Qs[idx] = g_Q[(size_t)t * 4 * E_DIM + idx];
    __syncthreads();

    int wid = tid >> 5, lane = tid & 31;
    const float RS = 0.04419417382415922f;  // 1/sqrt(512)
    for (int s = wid; s < S_SP; s += 8) {
        float acc[4] = {0.f, 0.f, 0.f, 0.f};
        const float* kr = &g_K[((size_t)t * S_SP + s) * E_DIM];
        for (int o = lane; o < E_DIM; o += 32) {
            float kv = kr[o];
            #pragma unroll
            for (int q = 0; q < 4; q++) acc[q] += kv * Qs[q * E_DIM + o];
        }
        #pragma unroll
        for (int off = 16; off; off >>= 1)
            #pragma unroll
            for (int q = 0; q < 4; q++) acc[q] += __shfl_xor_sync(0xffffffffu, acc[q], off);
        if (lane == 0) {
            #pragma unroll
            for (int q = 0; q < 4; q++) law[q * S_SP + s] = acc[q] * RS;
        }
    }
    __syncthreads();

    // softmax per q
    for (int q = 0; q < 4; q++) {
        float mx = -INFINITY;
        for (int s = tid; s < S_SP; s += 256) mx = fmaxf(mx, law[q * S_SP + s]);
        mx = blockMax256(mx);
        float lsum = 0.f;
        for (int s = tid; s < S_SP; s += 256) {
            float e = expf(law[q * S_SP + s] - mx);
            law[q * S_SP + s] = e;
            lsum += e;
        }
        float tot = blockSum256(lsum);
        float inv = 1.f / tot;
        for (int s = tid; s < S_SP; s += 256) law[q * S_SP + s] *= inv;
        __syncthreads();
    }

    // major = aw @ ov
    int nh = (tid < 128) ? 5 : 4;
    float macc[5][4];
    #pragma unroll
    for (int j = 0; j < 5; j++)
        #pragma unroll
        for (int q = 0; q < 4; q++) macc[j][q] = 0.f;
    const float* obase = ov + ((size_t)t * S_SP) * H_DIM + tid;
    for (int s = 0; s < S_SP; s++) {
        float a0 = law[0 * S_SP + s], a1 = law[1 * S_SP + s];
        float a2 = law[2 * S_SP + s], a3 = law[3 * S_SP + s];
        const float* p = obase + (size_t)s * H_DIM;
        #pragma unroll
        for (int j = 0; j < 5; j++) {
            if (j < nh) {
                float v = p[j * 256];
                macc[j][0] += a0 * v;
                macc[j][1] += a1 * v;
                macc[j][2] += a2 * v;
                macc[j][3] += a3 * v;
            }
        }
    }
    for (int j = 0; j < nh; j++) {
        int h = tid + j * 256;
        #pragma unroll
        for (int q = 0; q < 4; q++)
            out[OUT_MAJOR + ((size_t)t * 4 + q) * H_DIM + h] = macc[j][q];
    }
}

// ---------------- G: final = mean(m*g) / (mean(g)+1e-8) per image -------------
__global__ void k_final(float* __restrict__ out) {
    int b = blockIdx.x, tid = threadIdx.x;
    __shared__ float gsh[32];
    __shared__ float gsum_sh;
    if (tid < 32) {
        int p = tid >> 2, q = tid & 3;
        gsh[tid] = g_gsig[(b * P_PAT + p) * 4 + q];
    }
    __syncthreads();
    if (tid == 0) {
        float s = 0.f;
        for (int i = 0; i < 32; i++) s += gsh[i];
        gsum_sh = s;
    }
    __syncthreads();
    float denom = gsum_sh / 32.f + 1e-8f;
    int nh = (tid < 128) ? 5 : 4;
    for (int j = 0; j < nh; j++) {
        int h = tid + j * 256;
        float acc = 0.f;
        for (int idx = 0; idx < 32; idx++) {
            int p = idx >> 2, q = idx & 3;
            acc += out[OUT_MAJOR + ((size_t)(b * P_PAT + p) * 4 + q) * H_DIM + h] * gsh[idx];
        }
        float fin = (acc / 32.f) / denom;
        g_final[b * H_DIM + h] = fin;
        out[OUT_FINAL + (size_t)b * H_DIM + h] = fin;
    }
}

// ---------------- H: preds = softmax(gelu(final W1)W2) ------------------------
__global__ void k_preds(const float* __restrict__ w1, const float* __restrict__ b1,
                        const float* __restrict__ w2, const float* __restrict__ b2,
                        float* __restrict__ out) {
    int b = blockIdx.x, tid = threadIdx.x;
    __shared__ float fr[H_DIM];
    __shared__ float hid[E_DIM];
    __shared__ float lg[NE];
    for (int i = tid; i < H_DIM; i += 256) fr[i] = g_final[b * H_DIM + i];
    __syncthreads();
    int wid = tid >> 5, lane = tid & 31;
    for (int o = wid; o < E_DIM; o += 8) {
        float acc = 0.f;
        const float* wr = w1 + (size_t)o * H_DIM;
        for (int k = lane; k < H_DIM; k += 32) acc += wr[k] * fr[k];
        #pragma unroll
        for (int off = 16; off; off >>= 1) acc += __shfl_xor_sync(0xffffffffu, acc, off);
        if (lane == 0) hid[o] = gelu_exact(acc + b1[o]);
    }
    __syncthreads();
    for (int n = 0; n < NE; n++) {
        float v = hid[tid] * w2[n * E_DIM + tid] + hid[tid + 256] * w2[n * E_DIM + tid + 256];
        float tot = blockSum256(v);
        if (tid == 0) lg[n] = tot + b2[n];
    }
    __syncthreads();
    if (tid == 0) {
        float mx = -INFINITY;
        for (int n = 0; n < NE; n++) mx = fmaxf(mx, lg[n]);
        float sum = 0.f;
        float e[NE];
        for (int n = 0; n < NE; n++) { e[n] = expf(lg[n] - mx); sum += e[n]; }
        for (int n = 0; n < NE; n++) out[OUT_PREDS + b * NE + n] = e[n] / sum;
    }
}

// ---------------- launch -------------------------------------------------------
extern "C" void kernel_launch(void* const* d_in, const int* in_sizes, int n_in,
                              void* d_out, int out_size) {
    const float* ov      = (const float*)d_in[0];
    const float* sig     = (const float*)d_in[1];
    const float* emo     = (const float*)d_in[2];
    const float* pool_w  = (const float*)d_in[3];
    const float* pool_b  = (const float*)d_in[4];
    const float* cls_w1  = (const float*)d_in[5];
    const float* cls_b1  = (const float*)d_in[6];
    const float* cls_w2  = (const float*)d_in[7];
    const float* cls_b2  = (const float*)d_in[8];
    const float* sig_w   = (const float*)d_in[9];
    const float* sig_b   = (const float*)d_in[10];
    const float* prm_w   = (const float*)d_in[11];
    const float* prm_b   = (const float*)d_in[12];
    const float* pred_w1 = (const float*)d_in[13];
    const float* pred_b1 = (const float*)d_in[14];
    const float* pred_w2 = (const float*)d_in[15];
    const float* pred_b2 = (const float*)d_in[16];
    const float* q_w     = (const float*)d_in[17];
    const float* q_b     = (const float*)d_in[18];
    const float* k_w     = (const float*)d_in[19];
    const float* k_b     = (const float*)d_in[20];
    float* out = (float*)d_out;

    const int SIG_SMEM = (16384 + NE * E_DIM) * 4;  // 83968
    const int KP_SMEM  = (512 + 8192) * 4;          // 34816
    cudaFuncSetAttribute(k_sig_scores, cudaFuncAttributeMaxDynamicSharedMemorySize, SIG_SMEM);

    k_pool<<<B_IMG, 256>>>(ov, pool_w, pool_b);
    k_cls1<<<B_IMG, 256>>>(cls_w1, cls_b1);
    k_cls2<<<B_IMG, 256>>>(cls_w2, cls_b2);
    k_prompts<<<dim3(NE, B_IMG, NL), 256>>>(emo, prm_w, prm_b);
    k_sig_scores<<<dim3(23, T_TOK, NL), 256, SIG_SMEM>>>(sig, sig_w, sig_b);
    k_kproj<<<dim3(23, T_TOK, 1), 256, KP_SMEM>>>(ov, k_w, k_b);
    k_softmax_mean<<<T_TOK * NE, 256>>>();
    k_tokens<<<T_TOK, 256>>>(ov);
    k_qproj<<<T_TOK, 256>>>(q_w, q_b);
    k_attn_major<<<T_TOK, 256>>>(ov, out);
    k_final<<<B_IMG, 256>>>(out);
    k_preds<<<B_IMG, 256>>>(pred_w1, pred_b1, pred_w2, pred_b2, out);
}

// round 4
// speedup vs baseline: 1.9408x; 1.9408x over previous
#include <cuda_runtime.h>
#include <cuda_bf16.h>
#include <math.h>
#include <stdint.h>

// ---------------- problem constants ----------------
#define T_TOK 64
#define S_SP  729
#define H_DIM 1152
#define E_DIM 512
#define NE    9
#define NL    4
#define B_IMG 8
#define P_PAT 8

#define OUT_MAJOR 0
#define OUT_FINAL (T_TOK * 4 * H_DIM)                 // 294912
#define OUT_PREDS (OUT_FINAL + B_IMG * H_DIM)         // 304128

// ---------------- device scratch (static) ----------------
__device__ float g_pooled [B_IMG * H_DIM];
__device__ float g_hidden [B_IMG * E_DIM];
__device__ float g_cls    [B_IMG * E_DIM];
__device__ float g_puv    [NL * 17 * E_DIM];
__device__ float g_prompts[NL * B_IMG * NE * E_DIM];
__device__ float g_scores [(size_t)NL * T_TOK * NE * S_SP];   // 6.7 MB
__device__ float g_meanatt[T_TOK * NE * S_SP];
__device__ float g_pes    [T_TOK * NE];
__device__ float g_gsig   [T_TOK * 4];
__device__ float g_tokens [T_TOK * 4 * H_DIM];
__device__ float g_Q      [T_TOK * 4 * E_DIM];
__device__ float g_KQ     [T_TOK * 4 * H_DIM];
__device__ float g_qkb    [T_TOK * 4];
__device__ float g_final  [B_IMG * H_DIM];
__device__ __nv_bfloat16 g_Whi[(size_t)NL * E_DIM * H_DIM];
__device__ __nv_bfloat16 g_Wlo[(size_t)NL * E_DIM * H_DIM];

// ---------------- block reductions (blockDim 256) ----------------
__device__ __forceinline__ float blockSum256(float v) {
    __shared__ float red[8];
    int lane = threadIdx.x & 31, wid = threadIdx.x >> 5;
    #pragma unroll
    for (int o = 16; o; o >>= 1) v += __shfl_xor_sync(0xffffffffu, v, o);
    if (lane == 0) red[wid] = v;
    __syncthreads();
    if (wid == 0) {
        float r = (lane < 8) ? red[lane] : 0.f;
        #pragma unroll
        for (int o = 4; o; o >>= 1) r += __shfl_xor_sync(0xffffffffu, r, o);
        if (lane == 0) red[0] = r;
    }
    __syncthreads();
    float r = red[0];
    __syncthreads();
    return r;
}

__device__ __forceinline__ float blockMax256(float v) {
    __shared__ float red[8];
    int lane = threadIdx.x & 31, wid = threadIdx.x >> 5;
    #pragma unroll
    for (int o = 16; o; o >>= 1) v = fmaxf(v, __shfl_xor_sync(0xffffffffu, v, o));
    if (lane == 0) red[wid] = v;
    __syncthreads();
    if (wid == 0) {
        float r = (lane < 8) ? red[lane] : -INFINITY;
        #pragma unroll
        for (int o = 4; o; o >>= 1) r = fmaxf(r, __shfl_xor_sync(0xffffffffu, r, o));
        if (lane == 0) red[0] = r;
    }
    __syncthreads();
    float r = red[0];
    __syncthreads();
    return r;
}

__device__ __forceinline__ float gelu_exact(float x) {
    return 0.5f * x * (1.0f + erff(x * 0.7071067811865475f));
}

__device__ __forceinline__ uint32_t pk2(__nv_bfloat16 a, __nv_bfloat16 b) {
    return ((uint32_t)__bfloat16_as_ushort(b) << 16) | (uint32_t)__bfloat16_as_ushort(a);
}

// mma.sync m16n8k16 row.col f32.bf16.bf16.f32 (sm_80+ baseline feature)
__device__ __forceinline__ void mma16816(float* d, const uint32_t* a, uint32_t b0, uint32_t b1) {
    asm volatile(
        "mma.sync.aligned.m16n8k16.row.col.f32.bf16.bf16.f32 "
        "{%0,%1,%2,%3}, {%4,%5,%6,%7}, {%8,%9}, {%0,%1,%2,%3};"
        : "+f"(d[0]), "+f"(d[1]), "+f"(d[2]), "+f"(d[3])
        : "r"(a[0]), "r"(a[1]), "r"(a[2]), "r"(a[3]), "r"(b0), "r"(b1));
}

// ---------------- W split: fp32 -> bf16 hi/lo ----------------
__global__ void k_wsplit(const float* __restrict__ sw) {
    const size_t N = (size_t)NL * E_DIM * H_DIM;
    for (size_t i = (size_t)blockIdx.x * 256 + threadIdx.x; i < N; i += (size_t)gridDim.x * 256) {
        float w = sw[i];
        __nv_bfloat16 h = __float2bfloat16(w);
        g_Whi[i] = h;
        g_Wlo[i] = __float2bfloat16(w - __bfloat162float(h));
    }
}

// ---------------- P0: pooled ----------------
__global__ void k_pool(const float* __restrict__ ov, const float* __restrict__ pw,
                       const float* __restrict__ pb) {
    int b = blockIdx.x, tid = threadIdx.x;
    int nh = (tid < 128) ? 5 : 4;
    float acc[5] = {0, 0, 0, 0, 0};
    const float* base = ov + (size_t)(b * P_PAT) * S_SP * H_DIM + tid;
    for (int s = 0; s < S_SP; s++) {
        float w = pw[s];
        const float* p = base + (size_t)s * H_DIM;
        #pragma unroll
        for (int j = 0; j < 5; j++)
            if (j < nh) acc[j] += w * p[j * 256];
    }
    float bias = pb[0];
    for (int j = 0; j < nh; j++)
        g_pooled[b * H_DIM + tid + j * 256] = acc[j] + bias;
}

// ---------------- P1a / P1b ----------------
__global__ void k_cls1(const float* __restrict__ w1, const float* __restrict__ b1) {
    int b = blockIdx.x, tid = threadIdx.x;
    __shared__ float pr[H_DIM];
    for (int i = tid; i < H_DIM; i += 256) pr[i] = g_pooled[b * H_DIM + i];
    __syncthreads();
    int wid = tid >> 5, lane = tid & 31;
    for (int o = wid; o < E_DIM; o += 8) {
        float acc = 0.f;
        const float* wr = w1 + (size_t)o * H_DIM;
        for (int k = lane; k < H_DIM; k += 32) acc += wr[k] * pr[k];
        #pragma unroll
        for (int off = 16; off; off >>= 1) acc += __shfl_xor_sync(0xffffffffu, acc, off);
        if (lane == 0) g_hidden[b * E_DIM + o] = gelu_exact(acc + b1[o]);
    }
}

__global__ void k_cls2(const float* __restrict__ w2, const float* __restrict__ b2) {
    int b = blockIdx.x, tid = threadIdx.x;
    __shared__ float hr[E_DIM];
    for (int i = tid; i < E_DIM; i += 256) hr[i] = g_hidden[b * E_DIM + i];
    __syncthreads();
    int wid = tid >> 5, lane = tid & 31;
    for (int o = wid; o < E_DIM; o += 8) {
        float acc = 0.f;
        const float* wr = w2 + (size_t)o * E_DIM;
        for (int k = lane; k < E_DIM; k += 32) acc += wr[k] * hr[k];
        #pragma unroll
        for (int off = 16; off; off >>= 1) acc += __shfl_xor_sync(0xffffffffu, acc, off);
        if (lane == 0) g_cls[b * E_DIM + o] = acc + b2[o];
    }
}

// ---------------- prompt u/v factorization ----------------
__global__ void k_puv(const float* __restrict__ emo, const float* __restrict__ pw) {
    int oc = blockIdx.x;       // 0..7
    int i  = blockIdx.y;
    int tid = threadIdx.x, wid = tid >> 5, lane = tid & 31;
    __shared__ float es[NE * E_DIM];
    __shared__ float cs[B_IMG * E_DIM];
    for (int idx = tid; idx < NE * E_DIM; idx += 256) es[idx] = emo[idx];
    for (int idx = tid; idx < B_IMG * E_DIM; idx += 256) cs[idx] = g_cls[idx];
    __syncthreads();
    for (int oi = wid; oi < 64; oi += 8) {
        int o = oc * 64 + oi;
        const float* wr = pw + ((size_t)i * E_DIM + o) * 1024;
        float acc[17];
        #pragma unroll
        for (int j = 0; j < 17; j++) acc[j] = 0.f;
        for (int c = lane; c < 512; c += 32) {
            float w1 = wr[c];
            #pragma unroll
            for (int n = 0; n < NE; n++) acc[n] += w1 * es[n * 512 + c];
            float w2 = wr[512 + c];
            #pragma unroll
            for (int b = 0; b < B_IMG; b++) acc[9 + b] += w2 * cs[b * 512 + c];
        }
        #pragma unroll
        for (int j = 0; j < 17; j++) {
            #pragma unroll
            for (int off = 16; off; off >>= 1) acc[j] += __shfl_xor_sync(0xffffffffu, acc[j], off);
        }
        if (lane == 0) {
            #pragma unroll
            for (int j = 0; j < 17; j++) g_puv[((size_t)i * 17 + j) * 512 + o] = acc[j];
        }
    }
}

__global__ void k_prompts2(const float* __restrict__ pb) {
    int n = blockIdx.x, b = blockIdx.y, i = blockIdx.z;
    int tid = threadIdx.x;
    int o1 = tid, o2 = tid + 256;
    float r1 = g_puv[((size_t)i * 17 + n) * 512 + o1] + g_puv[((size_t)i * 17 + 9 + b) * 512 + o1]
             + pb[i * 512 + o1];
    float r2 = g_puv[((size_t)i * 17 + n) * 512 + o2] + g_puv[((size_t)i * 17 + 9 + b) * 512 + o2]
             + pb[i * 512 + o2];
    float nrm = blockSum256(r1 * r1 + r2 * r2);
    float inv = rsqrtf(nrm);
    size_t base = ((size_t)(i * B_IMG + b) * NE + n) * E_DIM;
    g_prompts[base + o1] = r1 * inv;
    g_prompts[base + o2] = r2 * inv;
}

// ================ A: mma.sync bf16 sig GEMM + fused epilogue ================
// grid (12, 64, 4), block 256 (8 warps: 2m x 4n). Tile M=64, N=512, kstep=32.
// Y[64s, 512o] = X[64s,1152h] @ W[512o,1152h]^T, 3-product hi/lo bf16 split.

// smem byte offsets
#define SM_PSM    0                         // 9*512 f32     = 18432
#define SM_SBI    18432                     // 512 f32       = 2048
#define SM_RED    20480                     // 64*10 f32     = 2560
#define SM_UNION  23040
#define SM_AHI    23040                     // 16*72 u32     = 4608
#define SM_ALO    27648                     // 4608
#define SM_WHI    32256                     // 16*520 u32    = 33280
#define SM_WLO    65536                     // 33280
#define SM_YSM    23040                     // 64*260 f32    = 66560 (union reuse)
#define SM_TOTAL  98816

#define A_STR 72
#define W_STR 520
#define Y_STR 260

__global__ void __launch_bounds__(256, 1)
k_sig_mma(const float* __restrict__ sig, const float* __restrict__ sb) {
    extern __shared__ char smem[];
    float*    Psm   = reinterpret_cast<float*>(smem + SM_PSM);
    float*    Sbi   = reinterpret_cast<float*>(smem + SM_SBI);
    float*    red   = reinterpret_cast<float*>(smem + SM_RED);
    uint32_t* AsmHi = reinterpret_cast<uint32_t*>(smem + SM_AHI);
    uint32_t* AsmLo = reinterpret_cast<uint32_t*>(smem + SM_ALO);
    uint32_t* WsmHi = reinterpret_cast<uint32_t*>(smem + SM_WHI);
    uint32_t* WsmLo = reinterpret_cast<uint32_t*>(smem + SM_WLO);
    float*    ysm   = reinterpret_cast<float*>(smem + SM_YSM);

    int tid = threadIdx.x;
    int wid = tid >> 5, lane = tid & 31;
    int wm = wid >> 2, wn = wid & 3;       // warp tile: rows wm*32.., cols wn*128..
    int g = lane >> 2, tig = lane & 3;

    int s0 = blockIdx.x * 64;
    int t  = blockIdx.y;
    int i  = blockIdx.z;
    int b  = t >> 3;

    // persist: prompts + bias + zero reduction buffer
    {
        size_t pbase = ((size_t)(i * B_IMG + b) * NE) * E_DIM;
        for (int idx = tid; idx < NE * E_DIM; idx += 256) Psm[idx] = g_prompts[pbase + idx];
        for (int idx = tid; idx < E_DIM; idx += 256) Sbi[idx] = sb[i * E_DIM + idx];
        for (int idx = tid; idx < 640; idx += 256) red[idx] = 0.f;
    }

    const float* Xbase = sig + ((size_t)(i * T_TOK + t) * S_SP) * H_DIM;
    const __nv_bfloat16* WHbase = g_Whi + (size_t)i * E_DIM * H_DIM;
    const __nv_bfloat16* WLbase = g_Wlo + (size_t)i * E_DIM * H_DIM;

    float acc[2][16][4];
    #pragma unroll
    for (int mt = 0; mt < 2; mt++)
        #pragma unroll
        for (int nt = 0; nt < 16; nt++)
            #pragma unroll
            for (int c = 0; c < 4; c++) acc[mt][nt][c] = 0.f;

    // X fill indices (fixed per thread)
    int xrow = tid >> 2, xkc = tid & 3;
    int xs = s0 + xrow;
    const float* xptr = (xs < S_SP) ? (Xbase + (size_t)xs * H_DIM + xkc * 8) : nullptr;

    const int NCH = H_DIM / 32;   // 36
    for (int ch = 0; ch < NCH; ch++) {
        __syncthreads();   // previous tiles consumed

        // ---- X tile: 64 rows x 32 k, fp32 -> hi/lo bf16 pairs
        {
            float xv[8];
            if (xptr) {
                const float* p = xptr + ch * 32;
                float4 f0 = *reinterpret_cast<const float4*>(p);
                float4 f1 = *reinterpret_cast<const float4*>(p + 4);
                xv[0]=f0.x; xv[1]=f0.y; xv[2]=f0.z; xv[3]=f0.w;
                xv[4]=f1.x; xv[5]=f1.y; xv[6]=f1.z; xv[7]=f1.w;
            } else {
                #pragma unroll
                for (int j = 0; j < 8; j++) xv[j] = 0.f;
            }
            #pragma unroll
            for (int j = 0; j < 4; j++) {
                __nv_bfloat16 h0 = __float2bfloat16(xv[2*j]);
                __nv_bfloat16 h1 = __float2bfloat16(xv[2*j+1]);
                __nv_bfloat16 l0 = __float2bfloat16(xv[2*j]   - __bfloat162float(h0));
                __nv_bfloat16 l1 = __float2bfloat16(xv[2*j+1] - __bfloat162float(h1));
                AsmHi[(xkc*4 + j) * A_STR + xrow] = pk2(h0, h1);
                AsmLo[(xkc*4 + j) * A_STR + xrow] = pk2(l0, l1);
            }
        }
        // ---- W tile: 512 n x 32 k, bf16 hi/lo copy into fragment layout
        #pragma unroll
        for (int rep = 0; rep < 2; rep++) {
            int n = tid + rep * 256;
            const uint4* hp = reinterpret_cast<const uint4*>(WHbase + (size_t)n * H_DIM + ch * 32);
            const uint4* lp = reinterpret_cast<const uint4*>(WLbase + (size_t)n * H_DIM + ch * 32);
            #pragma unroll
            for (int jj = 0; jj < 4; jj++) {
                uint4 qh = hp[jj];
                uint4 ql = lp[jj];
                WsmHi[(jj*4+0) * W_STR + n] = qh.x;
                WsmHi[(jj*4+1) * W_STR + n] = qh.y;
                WsmHi[(jj*4+2) * W_STR + n] = qh.z;
                WsmHi[(jj*4+3) * W_STR + n] = qh.w;
                WsmLo[(jj*4+0) * W_STR + n] = ql.x;
                WsmLo[(jj*4+1) * W_STR + n] = ql.y;
                WsmLo[(jj*4+2) * W_STR + n] = ql.z;
                WsmLo[(jj*4+3) * W_STR + n] = ql.w;
            }
        }
        __syncthreads();

        // ---- MMA: 2 x k16
        #pragma unroll
        for (int h = 0; h < 2; h++) {
            int kp = 8 * h + tig;
            uint32_t ahi[2][4], alo[2][4];
            #pragma unroll
            for (int mt = 0; mt < 2; mt++) {
                int r = wm * 32 + mt * 16 + g;
                ahi[mt][0] = AsmHi[kp * A_STR + r];
                ahi[mt][1] = AsmHi[kp * A_STR + r + 8];
                ahi[mt][2] = AsmHi[(kp + 4) * A_STR + r];
                ahi[mt][3] = AsmHi[(kp + 4) * A_STR + r + 8];
                alo[mt][0] = AsmLo[kp * A_STR + r];
                alo[mt][1] = AsmLo[kp * A_STR + r + 8];
                alo[mt][2] = AsmLo[(kp + 4) * A_STR + r];
                alo[mt][3] = AsmLo[(kp + 4) * A_STR + r + 8];
            }
            #pragma unroll
            for (int nt = 0; nt < 16; nt++) {
                int n = wn * 128 + nt * 8 + g;
                uint32_t b0h = WsmHi[kp * W_STR + n];
                uint32_t b1h = WsmHi[(kp + 4) * W_STR + n];
                uint32_t b0l = WsmLo[kp * W_STR + n];
                uint32_t b1l = WsmLo[(kp + 4) * W_STR + n];
                #pragma unroll
                for (int mt = 0; mt < 2; mt++) {
                    mma16816(acc[mt][nt], ahi[mt], b0h, b1h);
                    mma16816(acc[mt][nt], ahi[mt], b0l, b1l);
                    mma16816(acc[mt][nt], alo[mt], b0h, b1h);
                }
            }
        }
    }
    __syncthreads();

    // ---- epilogue: bias + L2 norm + 9 prompt dots, two N-halves via ysm
    for (int half = 0; half < 2; half++) {
        if ((wn >> 1) == half) {
            #pragma unroll
            for (int mt = 0; mt < 2; mt++) {
                int row = wm * 32 + mt * 16 + g;
                #pragma unroll
                for (int nt = 0; nt < 16; nt++) {
                    int col = wn * 128 + nt * 8 + tig * 2;
                    int colrel = col - half * 256;
                    float b0 = Sbi[col], b1 = Sbi[col + 1];
                    float2 v0 = make_float2(acc[mt][nt][0] + b0, acc[mt][nt][1] + b1);
                    float2 v1 = make_float2(acc[mt][nt][2] + b0, acc[mt][nt][3] + b1);
                    *reinterpret_cast<float2*>(&ysm[row * Y_STR + colrel]) = v0;
                    *reinterpret_cast<float2*>(&ysm[(row + 8) * Y_STR + colrel]) = v1;
                }
            }
        }
        __syncthreads();
        for (int r8 = 0; r8 < 8; r8++) {
            int row = wid * 8 + r8;
            float v[10];
            #pragma unroll
            for (int j = 0; j < 10; j++) v[j] = 0.f;
            for (int cc = lane; cc < 256; cc += 32) {
                float y = ysm[row * Y_STR + cc];
                int col = half * 256 + cc;
                v[0] += y * y;
                #pragma unroll
                for (int n = 0; n < NE; n++) v[1 + n] += y * Psm[n * 512 + col];
            }
            #pragma unroll
            for (int j = 0; j < 10; j++) {
                #pragma unroll
                for (int off = 16; off; off >>= 1) v[j] += __shfl_xor_sync(0xffffffffu, v[j], off);
            }
            if (lane == 0) {
                #pragma unroll
                for (int j = 0; j < 10; j++) red[row * 10 + j] += v[j];
            }
        }
        __syncthreads();
    }

    if (tid < 64) {
        int s = s0 + tid;
        if (s < S_SP) {
            float inv = rsqrtf(red[tid * 10]);
            size_t base = ((size_t)(i * T_TOK + t) * NE) * S_SP + s;
            #pragma unroll
            for (int n = 0; n < NE; n++)
                g_scores[base + (size_t)n * S_SP] = 100.f * red[tid * 10 + 1 + n] * inv;
        }
    }
}

// ---------------- B: softmax over s, mean over levels ----------------
__global__ void k_softmax_mean() {
    int tn = blockIdx.x;
    int t = tn / NE, n = tn % NE;
    int tid = threadIdx.x;
    float accm[3] = {0.f, 0.f, 0.f};
    for (int i = 0; i < NL; i++) {
        size_t base = ((size_t)(i * T_TOK + t) * NE + n) * S_SP;
        float x[3];
        float mx = -INFINITY;
        #pragma unroll
        for (int j = 0; j < 3; j++) {
            int s = tid + j * 256;
            x[j] = (s < S_SP) ? g_scores[base + s] : -INFINITY;
            mx = fmaxf(mx, x[j]);
        }
        mx = blockMax256(mx);
        float lsum = 0.f;
        float e[3];
        #pragma unroll
        for (int j = 0; j < 3; j++) {
            int s = tid + j * 256;
            e[j] = (s < S_SP) ? expf(x[j] - mx) : 0.f;
            lsum += e[j];
        }
        float tot = blockSum256(lsum);
        float inv = 0.25f / tot;
        #pragma unroll
        for (int j = 0; j < 3; j++) accm[j] += e[j] * inv;
    }
    float psum = 0.f;
    size_t obase = ((size_t)t * NE + n) * S_SP;
    #pragma unroll
    for (int j = 0; j < 3; j++) {
        int s = tid + j * 256;
        if (s < S_SP) {
            g_meanatt[obase + s] = accm[j];
            psum += accm[j];
        }
    }
    float tot = blockSum256(psum);
    if (tid == 0) g_pes[t * NE + n] = tot / (float)S_SP;
}

// ---------------- C: tokens + global_sig ----------------
__global__ void k_tokens(const float* __restrict__ ov) {
    int t = blockIdx.x, tid = threadIdx.x;
    __shared__ float matt[S_SP];
    __shared__ float sp[4];
    __shared__ float pmx;

    float bsum[4] = {0.f, 0.f, 0.f, 0.f};
    for (int s = tid; s < S_SP; s += 256) {
        float m = -INFINITY;
        #pragma unroll
        for (int n = 0; n < NE; n++)
            m = fmaxf(m, g_meanatt[((size_t)t * NE + n) * S_SP + s]);
        matt[s] = m;
        int r = s / 27, c = s - r * 27;
        bool r0 = r < 14, r1 = r >= 13, c0 = c < 14, c1 = c >= 13;
        if (r0 && c0) bsum[0] += m;
        if (r0 && c1) bsum[1] += m;
        if (r1 && c0) bsum[2] += m;
        if (r1 && c1) bsum[3] += m;
    }
    #pragma unroll
    for (int q = 0; q < 4; q++) {
        float tot = blockSum256(bsum[q]);
        if (tid == 0) sp[q] = tot / 196.f;
    }
    if (tid == 0) {
        float pm = -INFINITY;
        for (int n = 0; n < NE; n++) pm = fmaxf(pm, g_pes[t * NE + n]);
        pmx = pm;
    }
    __syncthreads();
    if (tid < 4) g_gsig[t * 4 + tid] = sp[tid] * pmx;

    int nh = (tid < 128) ? 5 : 4;
    float accT[5][4];
    #pragma unroll
    for (int j = 0; j < 5; j++)
        #pragma unroll
        for (int q = 0; q < 4; q++) accT[j][q] = 0.f;
    const float* obase = ov + ((size_t)t * S_SP) * H_DIM + tid;
    for (int s = 0; s < S_SP; s++) {
        float a = matt[s];
        int r = s / 27, c = s - r * 27;
        float w0 = (r < 14 && c < 14) ? a : 0.f;
        float w1 = (r < 14 && c >= 13) ? a : 0.f;
        float w2 = (r >= 13 && c < 14) ? a : 0.f;
        float w3 = (r >= 13 && c >= 13) ? a : 0.f;
        const float* p = obase + (size_t)s * H_DIM;
        #pragma unroll
        for (int j = 0; j < 5; j++) {
            if (j < nh) {
                float v = p[j * 256];
                accT[j][0] += v * w0;
                accT[j][1] += v * w1;
                accT[j][2] += v * w2;
                accT[j][3] += v * w3;
            }
        }
    }
    for (int j = 0; j < nh; j++) {
        int h = tid + j * 256;
        #pragma unroll
        for (int q = 0; q < 4; q++)
            g_tokens[((size_t)t * 4 + q) * H_DIM + h] =
                (accT[j][q] * (1.f / 196.f)) / (sp[q] + 1e-8f);
    }
}

// ---------------- E: Q projection ----------------
__global__ void k_qproj(const float* __restrict__ qw, const float* __restrict__ qb) {
    int t = blockIdx.x, tid = threadIdx.x;
    __shared__ float toks[4 * H_DIM];
    for (int idx = tid; idx < 4 * H_DIM; idx += 256) toks[idx] = g_tokens[(size_t)t * 4 * H_DIM + idx];
    __syncthreads();
    int wid = tid >> 5, lane = tid & 31;
    for (int o = wid; o < E_DIM; o += 8) {
        float acc[4] = {0.f, 0.f, 0.f, 0.f};
        const float* wr = qw + (size_t)o * H_DIM;
        for (int k = lane; k < H_DIM; k += 32) {
            float w = wr[k];
            #pragma unroll
            for (int q = 0; q < 4; q++) acc[q] += w * toks[q * H_DIM + k];
        }
        #pragma unroll
        for (int off = 16; off; off >>= 1)
            #pragma unroll
            for (int q = 0; q < 4; q++) acc[q] += __shfl_xor_sync(0xffffffffu, acc[q], off);
        if (lane == 0) {
            float bv = qb[o];
            #pragma unroll
            for (int q = 0; q < 4; q++) g_Q[((size_t)t * 4 + q) * E_DIM + o] = acc[q] + bv;
        }
    }
}

// ---------------- E2: KQ[t,q,h] = sum_e Q[t,q,e]*k_w[e,h]; qkb = Q.k_b --------
__global__ void k_kq(const float* __restrict__ kw, const float* __restrict__ kb) {
    int t = blockIdx.x, hc = blockIdx.y;   // hc 0..8 (H/128)
    int tid = threadIdx.x;
    __shared__ float Qs[4 * E_DIM];
    for (int idx = tid; idx < 4 * E_DIM; idx += 256) Qs[idx] = g_Q[(size_t)t * 4 * E_DIM + idx];
    __syncthreads();
    int h = hc * 128 + (tid >> 1);
    int q0 = (tid & 1) * 2;
    float a0 = 0.f, a1 = 0.f;
    const float* kcol = kw + h;
    for (int e = 0; e < E_DIM; e++) {
        float kv = kcol[(size_t)e * H_DIM];
        a0 += kv * Qs[(q0 + 0) * E_DIM + e];
        a1 += kv * Qs[(q0 + 1) * E_DIM + e];
    }
    g_KQ[((size_t)t * 4 + q0 + 0) * H_DIM + h] = a0;
    g_KQ[((size_t)t * 4 + q0 + 1) * H_DIM + h] = a1;

    if (hc == 0 && tid < 128) {
        int wid = tid >> 5, lane = tid & 31;
        float acc = 0.f;
        for (int e = lane; e < E_DIM; e += 32) acc += Qs[wid * E_DIM + e] * kb[e];
        #pragma unroll
        for (int off = 16; off; off >>= 1) acc += __shfl_xor_sync(0xffffffffu, acc, off);
        if (lane == 0) g_qkb[t * 4 + wid] = acc;
    }
}

// ---------------- F: q-former attention + major (K GEMM eliminated) -----------
__global__ void k_attn_major(const float* __restrict__ ov, float* __restrict__ out) {
    int t = blockIdx.x, tid = threadIdx.x;
    __shared__ float KQs[4 * H_DIM];
    __shared__ float law[4 * S_SP];
    __shared__ float qkbs[4];
    for (int idx = tid; idx < 4 * H_DIM; idx += 256) KQs[idx] = g_KQ[(size_t)t * 4 * H_DIM + idx];
    if (tid < 4) qkbs[tid] = g_qkb[t * 4 + tid];
    __syncthreads();

    int wid = tid >> 5, lane = tid & 31;
    const float RS = 0.04419417382415922f;  // 1/sqrt(512)
    for (int s = wid; s < S_SP; s += 8) {
        float acc[4] = {0.f, 0.f, 0.f, 0.f};
        const float* orow = ov + ((size_t)t * S_SP + s) * H_DIM;
        for (int h = lane; h < H_DIM; h += 32) {
            float vv = orow[h];
            #pragma unroll
            for (int q = 0; q < 4; q++) acc[q] += vv * KQs[q * H_DIM + h];
        }
        #pragma unroll
        for (int off = 16; off; off >>= 1)
            #pragma unroll
            for (int q = 0; q < 4; q++) acc[q] += __shfl_xor_sync(0xffffffffu, acc[q], off);
        if (lane == 0) {
            #pragma unroll
            for (int q = 0; q < 4; q++) law[q * S_SP + s] = (acc[q] + qkbs[q]) * RS;
        }
    }
    __syncthreads();

    for (int q = 0; q < 4; q++) {
        float mx = -INFINITY;
        for (int s = tid; s < S_SP; s += 256) mx = fmaxf(mx, law[q * S_SP + s]);
        mx = blockMax256(mx);
        float lsum = 0.f;
        for (int s = tid; s < S_SP; s += 256) {
            float e = expf(law[q * S_SP + s] - mx);
            law[q * S_SP + s] = e;
            lsum += e;
        }
        float tot = blockSum256(lsum);
        float inv = 1.f / tot;
        for (int s = tid; s < S_SP; s += 256) law[q * S_SP + s] *= inv;
        __syncthreads();
    }

    int nh = (tid < 128) ? 5 : 4;
    float macc[5][4];
    #pragma unroll
    for (int j = 0; j < 5; j++)
        #pragma unroll
        for (int q = 0; q < 4; q++) macc[j][q] = 0.f;
    const float* obase = ov + ((size_t)t * S_SP) * H_DIM + tid;
    for (int s = 0; s < S_SP; s++) {
        float a0 = law[0 * S_SP + s], a1 = law[1 * S_SP + s];
        float a2 = law[2 * S_SP + s], a3 = law[3 * S_SP + s];
        const float* p = obase + (size_t)s * H_DIM;
        #pragma unroll
        for (int j = 0; j < 5; j++) {
            if (j < nh) {
                float v = p[j * 256];
                macc[j][0] += a0 * v;
                macc[j][1] += a1 * v;
                macc[j][2] += a2 * v;
                macc[j][3] += a3 * v;
            }
        }
    }
    for (int j = 0; j < nh; j++) {
        int h = tid + j * 256;
        #pragma unroll
        for (int q = 0; q < 4; q++)
            out[OUT_MAJOR + ((size_t)t * 4 + q) * H_DIM + h] = macc[j][q];
    }
}

// ---------------- G: final ----------------
__global__ void k_final(float* __restrict__ out) {
    int b = blockIdx.x, tid = threadIdx.x;
    __shared__ float gsh[32];
    __shared__ float gsum_sh;
    if (tid < 32) {
        int p = tid >> 2, q = tid & 3;
        gsh[tid] = g_gsig[(b * P_PAT + p) * 4 + q];
    }
    __syncthreads();
    if (tid == 0) {
        float s = 0.f;
        for (int i = 0; i < 32; i++) s += gsh[i];
        gsum_sh = s;
    }
    __syncthreads();
    float denom = gsum_sh / 32.f + 1e-8f;
    int nh = (tid < 128) ? 5 : 4;
    for (int j = 0; j < nh; j++) {
        int h = tid + j * 256;
        float acc = 0.f;
        for (int idx = 0; idx < 32; idx++) {
            int p = idx >> 2, q = idx & 3;
            acc += out[OUT_MAJOR + ((size_t)(b * P_PAT + p) * 4 + q) * H_DIM + h] * gsh[idx];
        }
        float fin = (acc / 32.f) / denom;
        g_final[b * H_DIM + h] = fin;
        out[OUT_FINAL + (size_t)b * H_DIM + h] = fin;
    }
}

// ---------------- H: preds ----------------
__global__ void k_preds(const float* __restrict__ w1, const float* __restrict__ b1,
                        const float* __restrict__ w2, const float* __restrict__ b2,
                        float* __restrict__ out) {
    int b = blockIdx.x, tid = threadIdx.x;
    __shared__ float fr[H_DIM];
    __shared__ float hid[E_DIM];
    __shared__ float lg[NE];
    for (int i = tid; i < H_DIM; i += 256) fr[i] = g_final[b * H_DIM + i];
    __syncthreads();
    int wid = tid >> 5, lane = tid & 31;
    for (int o = wid; o < E_DIM; o += 8) {
        float acc = 0.f;
        const float* wr = w1 + (size_t)o * H_DIM;
        for (int k = lane; k < H_DIM; k += 32) acc += wr[k] * fr[k];
        #pragma unroll
        for (int off = 16; off; off >>= 1) acc += __shfl_xor_sync(0xffffffffu, acc, off);
        if (lane == 0) hid[o] = gelu_exact(acc + b1[o]);
    }
    __syncthreads();
    for (int n = 0; n < NE; n++) {
        float v = hid[tid] * w2[n * E_DIM + tid] + hid[tid + 256] * w2[n * E_DIM + tid + 256];
        float tot = blockSum256(v);
        if (tid == 0) lg[n] = tot + b2[n];
    }
    __syncthreads();
    if (tid == 0) {
        float mx = -INFINITY;
        for (int n = 0; n < NE; n++) mx = fmaxf(mx, lg[n]);
        float sum = 0.f;
        float e[NE];
        for (int n = 0; n < NE; n++) { e[n] = expf(lg[n] - mx); sum += e[n]; }
        for (int n = 0; n < NE; n++) out[OUT_PREDS + b * NE + n] = e[n] / sum;
    }
}

// ---------------- launch ----------------
extern "C" void kernel_launch(void* const* d_in, const int* in_sizes, int n_in,
                              void* d_out, int out_size) {
    const float* ov      = (const float*)d_in[0];
    const float* sig     = (const float*)d_in[1];
    const float* emo     = (const float*)d_in[2];
    const float* pool_w  = (const float*)d_in[3];
    const float* pool_b  = (const float*)d_in[4];
    const float* cls_w1  = (const float*)d_in[5];
    const float* cls_b1  = (const float*)d_in[6];
    const float* cls_w2  = (const float*)d_in[7];
    const float* cls_b2  = (const float*)d_in[8];
    const float* sig_w   = (const float*)d_in[9];
    const float* sig_b   = (const float*)d_in[10];
    const float* prm_w   = (const float*)d_in[11];
    const float* prm_b   = (const float*)d_in[12];
    const float* pred_w1 = (const float*)d_in[13];
    const float* pred_b1 = (const float*)d_in[14];
    const float* pred_w2 = (const float*)d_in[15];
    const float* pred_b2 = (const float*)d_in[16];
    const float* q_w     = (const float*)d_in[17];
    const float* q_b     = (const float*)d_in[18];
    const float* k_w     = (const float*)d_in[19];
    const float* k_b     = (const float*)d_in[20];
    float* out = (float*)d_out;

    cudaFuncSetAttribute(k_sig_mma, cudaFuncAttributeMaxDynamicSharedMemorySize, SM_TOTAL);

    k_wsplit<<<1024, 256>>>(sig_w);
    k_pool<<<B_IMG, 256>>>(ov, pool_w, pool_b);
    k_cls1<<<B_IMG, 256>>>(cls_w1, cls_b1);
    k_cls2<<<B_IMG, 256>>>(cls_w2, cls_b2);
    k_puv<<<dim3(8, NL), 256>>>(emo, prm_w);
    k_prompts2<<<dim3(NE, B_IMG, NL), 256>>>(prm_b);
    k_sig_mma<<<dim3(12, T_TOK, NL), 256, SM_TOTAL>>>(sig, sig_b);
    k_softmax_mean<<<T_TOK * NE, 256>>>();
    k_tokens<<<T_TOK, 256>>>(ov);
    k_qproj<<<T_TOK, 256>>>(q_w, q_b);
    k_kq<<<dim3(T_TOK, H_DIM / 128), 256>>>(k_w, k_b);
    k_attn_major<<<T_TOK, 256>>>(ov, out);
    k_final<<<B_IMG, 256>>>(out);
    k_preds<<<B_IMG, 256>>>(pred_w1, pred_b1, pred_w2, pred_b2, out);
}